// round 8
// baseline (speedup 1.0000x reference)
#include <cuda_runtime.h>
#include <cuda_fp16.h>

#define NN   50000
#define NNP  50048          // padded to 128
#define NE   800000
#define FIN  128
#define HID  72
#define HG   18             // HID/4
#define NLAY 3

// ---------------- scratch (static __device__, no allocations) ----------------
__device__ int      g_degi[NN];
__device__ float    g_dinv[NN];
__device__ int      g_off[NN + 1];
__device__ int      g_cur[NN];
__device__ int2     g_edge[NE];        // {src row, __float_as_int(norm)} CSR-by-col
__device__ unsigned g_h16[NNP * 80];   // h split fp16: [row][hi 0..79 | lo 80..159] halves
__device__ float    g_m[NN * HID];
__device__ float    g_agg[NN * HID];
__device__ float    g_statsL[NLAY][2 * HID];
__device__ float    g_C[160 * HID];    // folded edge-MLP weights (fp32)
__device__ float    g_bz[HID];
__device__ __half   g_wt[4][144 * 160]; // BN-folded split weights [col][hi 80 | lo 80]
__device__ float    g_biasF[4][144];    // BN-folded biases
__device__ uint2    g_mh[NN * HG];      // U packed half
__device__ uint2    g_aggh[NN * HG];    // V packed half
__device__ __half2  g_attr16[NE * 8];   // attr as fp16

// ---------------- helpers ----------------
__device__ __forceinline__ void fma4(float4& a, float s, const float4& b) {
    a.x = __fmaf_rn(s, b.x, a.x);
    a.y = __fmaf_rn(s, b.y, a.y);
    a.z = __fmaf_rn(s, b.z, a.z);
    a.w = __fmaf_rn(s, b.w, a.w);
}
__device__ __forceinline__ float tanh_fast(float x) {
    float e = __expf(2.0f * x);
    return 1.0f - __fdividef(2.0f, e + 1.0f);
}
__device__ __forceinline__ void mma16816(float* c, const unsigned* a,
                                         unsigned b0, unsigned b1) {
    asm volatile(
        "mma.sync.aligned.m16n8k16.row.col.f32.f16.f16.f32 "
        "{%0,%1,%2,%3}, {%4,%5,%6,%7}, {%8,%9}, {%0,%1,%2,%3};"
        : "+f"(c[0]), "+f"(c[1]), "+f"(c[2]), "+f"(c[3])
        : "r"(a[0]), "r"(a[1]), "r"(a[2]), "r"(a[3]), "r"(b0), "r"(b1));
}
// store a float4 as split fp16 (hi at base[idx], lo at base[20+idx])
__device__ __forceinline__ void store_split(uint2* base, int idx, float4 a) {
    __half hx = __float2half_rn(a.x), hy = __float2half_rn(a.y);
    __half hz = __float2half_rn(a.z), hw = __float2half_rn(a.w);
    __half2 plo = __halves2half2(hx, hy), phi = __halves2half2(hz, hw);
    base[idx] = make_uint2(*reinterpret_cast<unsigned*>(&plo),
                           *reinterpret_cast<unsigned*>(&phi));
    __half2 llo = __floats2half2_rn(a.x - __half2float(hx), a.y - __half2float(hy));
    __half2 lhi = __floats2half2_rn(a.z - __half2float(hz), a.w - __half2float(hw));
    base[20 + idx] = make_uint2(*reinterpret_cast<unsigned*>(&llo),
                                *reinterpret_cast<unsigned*>(&lhi));
}

// ---------------- graph preprocessing ----------------
__global__ void k_zero() {
    int i = blockIdx.x * blockDim.x + threadIdx.x;
    if (i < NN) g_degi[i] = 0;
    if (i < NLAY * 2 * HID) ((float*)g_statsL)[i] = 0.f;
}
__global__ void k_deg(const int* __restrict__ col) {
    int e = blockIdx.x * blockDim.x + threadIdx.x;
    if (e < NE) atomicAdd(&g_degi[col[e]], 1);
}
__global__ void k_attr16(const float* __restrict__ attr) {
    int i = blockIdx.x * blockDim.x + threadIdx.x;
    if (i < NE * 8) {
        float2 v = ((const float2*)attr)[i];
        g_attr16[i] = __floats2half2_rn(v.x, v.y);
    }
}
__global__ void k_scan() {
    __shared__ int sp[1024];
    int tid = threadIdx.x;
    const int CH = (NN + 1023) / 1024;  // 49
    int start = tid * CH;
    int end = min(start + CH, NN);
    int loc = 0;
    for (int i = start; i < end; i++) loc += g_degi[i];
    sp[tid] = loc;
    __syncthreads();
    for (int off = 1; off < 1024; off <<= 1) {
        int v = (tid >= off) ? sp[tid - off] : 0;
        __syncthreads();
        sp[tid] += v;
        __syncthreads();
    }
    int run = sp[tid] - loc;
    for (int i = start; i < end; i++) {
        int d = g_degi[i];
        g_off[i] = run;
        g_cur[i] = run;
        run += d;
        g_dinv[i] = (d > 0) ? rsqrtf((float)d) : 0.0f;
    }
    if (tid == 1023) g_off[NN] = NE;
}
__global__ void k_sort(const int* __restrict__ row, const int* __restrict__ col) {
    int e = blockIdx.x * blockDim.x + threadIdx.x;
    if (e < NE) {
        int r = row[e], c = col[e];
        float nrm = g_dinv[r] * g_dinv[c];
        int p = atomicAdd(&g_cur[c], 1);
        g_edge[p] = make_int2(r, __float_as_int(nrm));
    }
}

// ---------------- weight prep: fold BN, split fp16 hi/lo. Warp per column. ----------------
__global__ void __launch_bounds__(256) k_prep(const float* __restrict__ Wa,
                                              const float* __restrict__ Wb,
                                              const float* __restrict__ bias_b,
                                              const float* __restrict__ gamma,
                                              const float* __restrict__ beta,
                                              const float* __restrict__ stats,
                                              __half* __restrict__ wt,
                                              float* __restrict__ biasOut) {
    __shared__ float sc[HID], sh[HID];
    int tid = threadIdx.x;
    if (tid < HID) {
        if (gamma != nullptr) {
            float S = __ldg(&stats[tid]), Q = __ldg(&stats[HID + tid]);
            float mu = S * (1.0f / NN);
            float var = Q * (1.0f / NN) - mu * mu;
            float s = __ldg(&gamma[tid]) * rsqrtf(var + 1e-5f);
            sc[tid] = s;
            sh[tid] = __ldg(&beta[tid]) - mu * s;
        } else {
            sc[tid] = 1.0f;
            sh[tid] = 0.0f;
        }
    }
    __syncthreads();
    int col = blockIdx.x * 8 + (tid >> 5);   // 0..143
    int lane = tid & 31;
    const float* Wsrc = (col < HID) ? Wa : Wb;
    int j = (col < HID) ? col : col - HID;
    float bsum = 0.f;
    for (int kk = lane; kk < 80; kk += 32) {
        __half hi = __float2half_rn(0.f), lo = hi;
        if (kk < HID) {
            float w = __ldg(&Wsrc[kk * HID + j]);
            float ws = w * sc[kk];
            hi = __float2half_rn(ws);
            lo = __float2half_rn(ws - __half2float(hi));
            bsum = __fmaf_rn(sh[kk], w, bsum);
        }
        wt[col * 160 + kk] = hi;
        wt[col * 160 + 80 + kk] = lo;
    }
#pragma unroll
    for (int off = 16; off; off >>= 1)
        bsum += __shfl_xor_sync(0xffffffffu, bsum, off);
    if (lane == 0)
        biasOut[col] = bsum + ((bias_b != nullptr && col >= HID) ? __ldg(&bias_b[j]) : 0.f);
}

// ---------------- node_lin (FFMA, writes split fp16 h) ----------------
__global__ void __launch_bounds__(288, 4) k_node_lin(const float* __restrict__ x,
                                                     const float* __restrict__ W,
                                                     const float* __restrict__ b) {
    __shared__ float4 sW[32 * HG];
    __shared__ float  sxT[32 * 100];
    int tid = threadIdx.x;
    int tx = tid % 9, ty = tid / 9;      // ty 0..31
    int n0 = blockIdx.x * 96;
    const float4* W4 = (const float4*)W;
    const float4* x4 = (const float4*)x;
    float4 acc0[3], acc1[3];
    float4 b0 = __ldg(&((const float4*)b)[tx]);
    float4 b1 = __ldg(&((const float4*)b)[tx + 9]);
#pragma unroll
    for (int i = 0; i < 3; i++) { acc0[i] = b0; acc1[i] = b1; }

    for (int c = 0; c < 4; c++) {
        __syncthreads();
        for (int i = tid; i < 32 * HG; i += 288) {
            int kk = i / HG, j = i % HG;
            sW[i] = W4[(c * 32 + kk) * HG + j];
        }
        for (int i = tid; i < 96 * 8; i += 288) {
            int n = i >> 3, kq = i & 7;
            int gn = n0 + n;
            float4 v = make_float4(0.f, 0.f, 0.f, 0.f);
            if (gn < NN) v = x4[gn * 32 + c * 8 + kq];
            sxT[(4 * kq + 0) * 100 + n] = v.x;
            sxT[(4 * kq + 1) * 100 + n] = v.y;
            sxT[(4 * kq + 2) * 100 + n] = v.z;
            sxT[(4 * kq + 3) * 100 + n] = v.w;
        }
        __syncthreads();
#pragma unroll 4
        for (int k = 0; k < 32; k++) {
            float4 w0 = sW[k * HG + tx];
            float4 w1 = sW[k * HG + tx + 9];
            float xv[3];
#pragma unroll
            for (int i = 0; i < 3; i++) xv[i] = sxT[k * 100 + ty * 3 + i];
#pragma unroll
            for (int i = 0; i < 3; i++) {
                fma4(acc0[i], xv[i], w0);
                fma4(acc1[i], xv[i], w1);
            }
        }
    }
#pragma unroll
    for (int i = 0; i < 3; i++) {
        int n = n0 + ty * 3 + i;
        if (n < NN) {
            uint2* base = ((uint2*)g_h16) + (size_t)n * 40;
            float4 a = acc0[i];
            a.x = fmaxf(a.x, 0.f); a.y = fmaxf(a.y, 0.f);
            a.z = fmaxf(a.z, 0.f); a.w = fmaxf(a.w, 0.f);
            store_split(base, tx, a);
            a = acc1[i];
            a.x = fmaxf(a.x, 0.f); a.y = fmaxf(a.y, 0.f);
            a.z = fmaxf(a.z, 0.f); a.w = fmaxf(a.w, 0.f);
            store_split(base, tx + 9, a);
            if (tx < 2) {   // zero pads (cols 72..79 of hi and lo)
                base[18 + tx] = make_uint2(0u, 0u);
                base[38 + tx] = make_uint2(0u, 0u);
            }
        }
    }
}

// ---------------- tensor-core dual GEMM with split-fp16 precision ----------------
// [m|agg] = h @ wt + bias via up to 3 MMA terms: hi*Whi + lo*Whi + hi*Wlo.
// 128 nodes/block, 8 warps (4 M x 2 N-halves). No smem, no syncs.
__global__ void __launch_bounds__(256, 2) k_dualgemm_tc(const __half* __restrict__ wt,
                                                        const float* __restrict__ bias,
                                                        int nterms, int half_out) {
    int wid = threadIdx.x >> 5, lane = threadIdx.x & 31;
    int g = lane >> 2, t = lane & 3;
    int warpM = wid >> 1, warpN = wid & 1;
    int n0 = blockIdx.x * 128 + warpM * 32;
    const unsigned* h32 = g_h16;                 // row stride 80 u32
    const unsigned* w32 = (const unsigned*)wt;   // col stride 80 u32

    float acc[2][9][4];
#pragma unroll
    for (int fr = 0; fr < 2; fr++)
#pragma unroll
        for (int f = 0; f < 9; f++)
#pragma unroll
            for (int q = 0; q < 4; q++) acc[fr][f][q] = 0.0f;

    const unsigned* wbase = w32 + (size_t)(warpN * 72 + g) * 80 + t;
    const unsigned* hbase = h32 + (size_t)(n0 + g) * 80 + t;

#pragma unroll
    for (int tm = 0; tm < 3; tm++) {
        if (tm >= nterms) break;
        int aoff = (tm == 1) ? 40 : 0;   // lo segment of h
        int boff = (tm == 2) ? 40 : 0;   // lo segment of W
#pragma unroll
        for (int kc = 0; kc < 5; kc++) {
            int ka = aoff + kc * 8;
            int kb = boff + kc * 8;
            unsigned a[2][4];
#pragma unroll
            for (int fr = 0; fr < 2; fr++) {
                const unsigned* hp = hbase + fr * (16 * 80) + ka;
                a[fr][0] = __ldg(hp);
                a[fr][2] = __ldg(hp + 4);
                a[fr][1] = __ldg(hp + 8 * 80);
                a[fr][3] = __ldg(hp + 8 * 80 + 4);
            }
#pragma unroll
            for (int f = 0; f < 9; f++) {
                const unsigned* wp = wbase + f * (8 * 80) + kb;
                unsigned b0 = __ldg(wp);
                unsigned b1 = __ldg(wp + 4);
                mma16816(acc[0][f], a[0], b0, b1);
                mma16816(acc[1][f], a[1], b0, b1);
            }
        }
    }

#pragma unroll
    for (int fr = 0; fr < 2; fr++) {
        int r0 = n0 + fr * 16 + g;
#pragma unroll
        for (int f = 0; f < 9; f++) {
            int colg = warpN * 72 + f * 8 + 2 * t;
            float2 bv = *(const float2*)&bias[colg];
            int lcol = f * 8 + 2 * t;
            float d0 = acc[fr][f][0] + bv.x, d1 = acc[fr][f][1] + bv.y;
            float d2 = acc[fr][f][2] + bv.x, d3 = acc[fr][f][3] + bv.y;
            if (!half_out) {
                float* outp = warpN ? g_agg : g_m;
                if (r0 < NN) *(float2*)&outp[r0 * HID + lcol] = make_float2(d0, d1);
                if (r0 + 8 < NN) *(float2*)&outp[(r0 + 8) * HID + lcol] = make_float2(d2, d3);
            } else {
                unsigned* outp = warpN ? (unsigned*)g_aggh : (unsigned*)g_mh;
                if (r0 < NN) {
                    __half2 p = __floats2half2_rn(d0, d1);
                    outp[r0 * 36 + (lcol >> 1)] = *reinterpret_cast<unsigned*>(&p);
                }
                if (r0 + 8 < NN) {
                    __half2 p = __floats2half2_rn(d2, d3);
                    outp[(r0 + 8) * 36 + (lcol >> 1)] = *reinterpret_cast<unsigned*>(&p);
                }
            }
        }
    }
}

// gather aggregation + relu + BN-stats fused. 16 nodes/block. Writes split fp16 h.
__global__ void __launch_bounds__(288) k_aggregate(float* __restrict__ stats) {
    int tx = threadIdx.x, ty = threadIdx.y;
    int n = blockIdx.x * 16 + ty;     // NN = 3125*16 exact
    int s = g_off[n], e = g_off[n + 1];
    const float4* m4 = (const float4*)g_m;
    float4 acc = ((const float4*)g_agg)[n * HG + tx];
    int j = s;
    for (; j + 3 < e; j += 4) {
        int2 e0 = __ldg(&g_edge[j]);
        int2 e1 = __ldg(&g_edge[j + 1]);
        int2 e2 = __ldg(&g_edge[j + 2]);
        int2 e3 = __ldg(&g_edge[j + 3]);
        float4 v0 = __ldg(&m4[e0.x * HG + tx]);
        float4 v1 = __ldg(&m4[e1.x * HG + tx]);
        float4 v2 = __ldg(&m4[e2.x * HG + tx]);
        float4 v3 = __ldg(&m4[e3.x * HG + tx]);
        fma4(acc, __int_as_float(e0.y), v0);
        fma4(acc, __int_as_float(e1.y), v1);
        fma4(acc, __int_as_float(e2.y), v2);
        fma4(acc, __int_as_float(e3.y), v3);
    }
    for (; j < e; j++) {
        int2 e0 = __ldg(&g_edge[j]);
        fma4(acc, __int_as_float(e0.y), __ldg(&m4[e0.x * HG + tx]));
    }
    acc.x = fmaxf(acc.x, 0.f); acc.y = fmaxf(acc.y, 0.f);
    acc.z = fmaxf(acc.z, 0.f); acc.w = fmaxf(acc.w, 0.f);
    {
        uint2* base = ((uint2*)g_h16) + (size_t)n * 40;
        store_split(base, tx, acc);
        if (tx < 2) {
            base[18 + tx] = make_uint2(0u, 0u);
            base[38 + tx] = make_uint2(0u, 0u);
        }
    }

    __shared__ float4 red[2][16][19];
    float4 sq;
    sq.x = acc.x * acc.x; sq.y = acc.y * acc.y;
    sq.z = acc.z * acc.z; sq.w = acc.w * acc.w;
    red[0][ty][tx] = acc;
    red[1][ty][tx] = sq;
    __syncthreads();
    if (ty == 0) {
        float4 S = make_float4(0.f, 0.f, 0.f, 0.f);
        float4 Q = make_float4(0.f, 0.f, 0.f, 0.f);
#pragma unroll
        for (int r = 0; r < 16; r++) {
            float4 a = red[0][r][tx], q = red[1][r][tx];
            S.x += a.x; S.y += a.y; S.z += a.z; S.w += a.w;
            Q.x += q.x; Q.y += q.y; Q.z += q.z; Q.w += q.w;
        }
        atomicAdd(&stats[tx * 4 + 0], S.x);
        atomicAdd(&stats[tx * 4 + 1], S.y);
        atomicAdd(&stats[tx * 4 + 2], S.z);
        atomicAdd(&stats[tx * 4 + 3], S.w);
        atomicAdd(&stats[HID + tx * 4 + 0], Q.x);
        atomicAdd(&stats[HID + tx * 4 + 1], Q.y);
        atomicAdd(&stats[HID + tx * 4 + 2], Q.z);
        atomicAdd(&stats[HID + tx * 4 + 3], Q.w);
    }
}

// fold edge-MLP front-end: C[160][72], bz[72]
__global__ void __launch_bounds__(288) k_fold(const float* __restrict__ W1,
                                              const float* __restrict__ W2,
                                              const float* __restrict__ M1,
                                              const float* __restrict__ b1,
                                              const float* __restrict__ b2,
                                              const float* __restrict__ bm) {
    __shared__ float4 sM1[144 * HG];
    int tid = threadIdx.x;
    const float4* M1_4 = (const float4*)M1;
    for (int i = tid; i < 144 * HG; i += 288) sM1[i] = M1_4[i];
    __syncthreads();
    int rowi = blockIdx.x * 16 + tid / HG;
    int chg = tid % HG;
    if (rowi < 160) {
        float4 acc = make_float4(0.f, 0.f, 0.f, 0.f);
        if (rowi < 144) {
#pragma unroll 8
            for (int k = 0; k < HID; k++)
                fma4(acc, __ldg(&W1[rowi * HID + k]), sM1[k * HG + chg]);
        } else {
            int r2 = rowi - 144;
#pragma unroll
            for (int k = 0; k < HID; k++)
                fma4(acc, __ldg(&W2[r2 * HID + k]), sM1[(HID + k) * HG + chg]);
        }
        ((float4*)g_C)[rowi * HG + chg] = acc;
    }
    if (blockIdx.x == 0 && tid < HG) {
        float4 acc = __ldg(&((const float4*)bm)[tid]);
#pragma unroll 8
        for (int k = 0; k < HID; k++) {
            fma4(acc, __ldg(&b1[k]), sM1[k * HG + tid]);
            fma4(acc, __ldg(&b2[k]), sM1[(HID + k) * HG + tid]);
        }
        ((float4*)g_bz)[tid] = acc;
    }
}

// final per-edge stage: z = U[r] + V[c] + attr@C3 + bz; out = tanh(z).w2 + b2m
// attr read as fp16 (precomputed); broadcast via PRMT, HFMA2 accumulate.
__global__ void __launch_bounds__(288, 3) k_edge(const int* __restrict__ row,
                                                 const int* __restrict__ col,
                                                 const float* __restrict__ w2,
                                                 const float* __restrict__ b2m,
                                                 float* __restrict__ out) {
    __shared__ float shp[4][288];
    int tid = threadIdx.x;
    int el = tid / HG;          // 0..15
    int chg = tid - el * HG;    // 0..17
    const float4* C3_4 = (const float4*)(g_C + 144 * HID);
    __half2 c3l[16], c3h[16];
#pragma unroll
    for (int k = 0; k < 16; k++) {
        float4 tt = __ldg(&C3_4[k * HG + chg]);
        c3l[k] = __floats2half2_rn(tt.x, tt.y);
        c3h[k] = __floats2half2_rn(tt.z, tt.w);
    }
    float4 bz = __ldg(&((const float4*)g_bz)[chg]);
    float4 wv = __ldg(&((const float4*)w2)[chg]);
    float bout = __ldg(b2m);
    const uint4* at4 = (const uint4*)g_attr16;   // 2 uint4 per edge
    const int nrounds = NE / 64;   // 12500
    for (int rd = blockIdx.x; rd < nrounds; rd += gridDim.x) {
        int ebase = rd * 64 + el;
#pragma unroll
        for (int s = 0; s < 4; s++) {
            int e = ebase + s * 16;
            int r = __ldg(&row[e]);
            int c = __ldg(&col[e]);
            uint2 up = __ldg(&g_mh[r * HG + chg]);
            uint2 vp = __ldg(&g_aggh[c * HG + chg]);
            float2 ulo = __half22float2(*reinterpret_cast<__half2*>(&up.x));
            float2 uhi = __half22float2(*reinterpret_cast<__half2*>(&up.y));
            float2 vlo = __half22float2(*reinterpret_cast<__half2*>(&vp.x));
            float2 vhi = __half22float2(*reinterpret_cast<__half2*>(&vp.y));
            uint4 p0 = __ldg(&at4[e * 2]);
            uint4 p1 = __ldg(&at4[e * 2 + 1]);
            unsigned pk[8] = {p0.x, p0.y, p0.z, p0.w, p1.x, p1.y, p1.z, p1.w};
            __half2 accl = __float2half2_rn(0.f);
            __half2 acch = __float2half2_rn(0.f);
#pragma unroll
            for (int k = 0; k < 8; k++) {
                __half2 pp = *reinterpret_cast<__half2*>(&pk[k]);
                __half2 bl = __low2half2(pp);
                __half2 bh = __high2half2(pp);
                accl = __hfma2(bl, c3l[2 * k], accl);
                acch = __hfma2(bl, c3h[2 * k], acch);
                accl = __hfma2(bh, c3l[2 * k + 1], accl);
                acch = __hfma2(bh, c3h[2 * k + 1], acch);
            }
            float2 fl = __half22float2(accl);
            float2 fh = __half22float2(acch);
            float4 z;
            z.x = ulo.x + vlo.x + bz.x + fl.x;
            z.y = ulo.y + vlo.y + bz.y + fl.y;
            z.z = uhi.x + vhi.x + bz.z + fh.x;
            z.w = uhi.y + vhi.y + bz.w + fh.y;
            shp[s][tid] = tanh_fast(z.x) * wv.x + tanh_fast(z.y) * wv.y +
                          tanh_fast(z.z) * wv.z + tanh_fast(z.w) * wv.w;
        }
        __syncthreads();
        if (tid < 64) {
            int sSel = tid >> 4, e_l = tid & 15;
            float ss = 0.f;
#pragma unroll
            for (int jj = 0; jj < HG; jj++) ss += shp[sSel][e_l * HG + jj];
            out[rd * 64 + tid] = ss + bout;
        }
        __syncthreads();
    }
}

// ---------------- launch ----------------
extern "C" void kernel_launch(void* const* d_in, const int* in_sizes, int n_in,
                              void* d_out, int out_size) {
    const float* x     = (const float*)d_in[0];
    const int*   ei    = (const int*)d_in[1];
    const float* attr  = (const float*)d_in[2];
    const float* nlw   = (const float*)d_in[3];
    const float* nlb   = (const float*)d_in[4];
    const float* convw = (const float*)d_in[5];
    const float* convv = (const float*)d_in[6];
    const float* convb = (const float*)d_in[7];
    const float* gamma = (const float*)d_in[8];
    const float* beta  = (const float*)d_in[9];
    const float* W1    = (const float*)d_in[10];
    const float* b1    = (const float*)d_in[11];
    const float* W2    = (const float*)d_in[12];
    const float* b2e   = (const float*)d_in[13];
    const float* M1    = (const float*)d_in[14];
    const float* bm    = (const float*)d_in[15];
    const float* w2    = (const float*)d_in[16];
    const float* b2m   = (const float*)d_in[17];
    const int* row = ei;
    const int* col = ei + NE;
    float* out = (float*)d_out;

    float*  pC = nullptr;
    float*  pStats = nullptr;
    __half* pWt = nullptr;
    float*  pBias = nullptr;
    cudaGetSymbolAddress((void**)&pC, g_C);
    cudaGetSymbolAddress((void**)&pStats, g_statsL);
    cudaGetSymbolAddress((void**)&pWt, g_wt);
    cudaGetSymbolAddress((void**)&pBias, g_biasF);

    const int GBN = (NN + 95) / 96;    // 521 (node_lin)
    const int GBT = NNP / 128;         // 391 (tc gemm)

    k_prep<<<18, 256>>>(convw, convv, convb, nullptr, nullptr, nullptr,    // 0
                        pWt, pBias);
    k_node_lin<<<GBN, 288>>>(x, nlw, nlb);                                 // 1
    k_zero<<<(NN + 255) / 256, 256>>>();                                   // 2
    k_dualgemm_tc<<<GBT, 256>>>(pWt, pBias, 3, 0);                         // 3 (profiled)
    k_deg<<<(NE + 255) / 256, 256>>>(col);                                 // 4
    k_attr16<<<(NE * 8 + 255) / 256, 256>>>(attr);                         // 5
    k_scan<<<1, 1024>>>();                                                 // 6
    k_sort<<<(NE + 255) / 256, 256>>>(row, col);                           // 7
    k_aggregate<<<3125, dim3(HG, 16)>>>(pStats);                           // 8
    for (int t = 1; t < NLAY; t++) {
        k_prep<<<18, 256>>>(convw + t * HID * HID, convv + t * HID * HID,
                            convb + t * HID,
                            gamma + (t - 1) * HID, beta + (t - 1) * HID,
                            pStats + (t - 1) * 2 * HID,
                            pWt + t * 144 * 160, pBias + t * 144);
        k_dualgemm_tc<<<GBT, 256>>>(pWt + t * 144 * 160, pBias + t * 144, 3, 0);
        k_aggregate<<<3125, dim3(HG, 16)>>>(pStats + t * 2 * HID);
    }
    k_fold<<<10, 288>>>(W1, W2, M1, b1, b2e, bm);
    k_prep<<<18, 256>>>(pC, pC + HID * HID, nullptr,
                        gamma + (NLAY - 1) * HID, beta + (NLAY - 1) * HID,
                        pStats + (NLAY - 1) * 2 * HID,
                        pWt + 3 * 144 * 160, pBias + 3 * 144);
    k_dualgemm_tc<<<GBT, 256>>>(pWt + 3 * 144 * 160, pBias + 3 * 144, 1, 1);
    k_edge<<<1850, 288>>>(row, col, w2, b2m, out);
}